// round 15
// baseline (speedup 1.0000x reference)
#include <cuda_runtime.h>

#define NB 512      // batch
#define NT 1024     // time steps
#define HID 64      // hidden
#define NG 192      // 3 * HID gates

// Scratch (static __device__ arrays; allocation-free per harness rules)
__device__ float g_xgA[(size_t)NT * NB * NG];  // xg for layers 2,4
__device__ float g_xgB[(size_t)NT * NB * NG];  // xg for layers 1,3
__device__ float g_h0[(size_t)NT * NB * HID];  // layer outputs ping
__device__ float g_h1[(size_t)NT * NB * HID];  // pong

__device__ __forceinline__ float sigf(float x) {
    return __fdividef(1.f, 1.f + __expf(-x));
}
__device__ __forceinline__ float tanh_(float x) {
    return fmaf(2.f, sigf(2.f * x), -1.f);
}

// packed fp32x2 ops
__device__ __forceinline__ unsigned long long ffma2(unsigned long long a,
                                                    unsigned long long b,
                                                    unsigned long long c) {
    unsigned long long d;
    asm("fma.rn.f32x2 %0, %1, %2, %3;" : "=l"(d) : "l"(a), "l"(b), "l"(c));
    return d;
}
__device__ __forceinline__ unsigned long long fadd2(unsigned long long a,
                                                    unsigned long long b) {
    unsigned long long d;
    asm("add.rn.f32x2 %0, %1, %2;" : "=l"(d) : "l"(a), "l"(b));
    return d;
}
__device__ __forceinline__ float f2sum(unsigned long long v) {
    return __uint_as_float((unsigned)v) + __uint_as_float((unsigned)(v >> 32));
}

// tf32 helpers
__device__ __forceinline__ unsigned cvt_tf32(float x) {
    unsigned u;
    asm("cvt.rna.tf32.f32 %0, %1;" : "=r"(u) : "f"(x));
    return u;
}
__device__ __forceinline__ void mma_tf32(float* d,
                                         unsigned a0, unsigned a1,
                                         unsigned a2, unsigned a3,
                                         unsigned b0, unsigned b1) {
    asm("mma.sync.aligned.m16n8k8.row.col.f32.tf32.tf32.f32 "
        "{%0,%1,%2,%3}, {%4,%5,%6,%7}, {%8,%9}, {%0,%1,%2,%3};"
        : "+f"(d[0]), "+f"(d[1]), "+f"(d[2]), "+f"(d[3])
        : "r"(a0), "r"(a1), "r"(a2), "r"(a3), "r"(b0), "r"(b1));
}

// ---------------------------------------------------------------------------
// Layer-0 FUSED scan: input dot (dim 5) computed inline — no xg round-trip.
// Same structure as k_scan (split-K lane pairs, 384 thr, 2 rows/CTA).
// x is [B][T][5]; a 10-float tile per CTA staged in smem, double-buffered.
// Gate order (torch): r=[0:64), z=[64:128), n=[128:192).
// ---------------------------------------------------------------------------
__global__ __launch_bounds__(384, 2)
void k_scan0(const float* __restrict__ x,
             const float* __restrict__ w_ih0,
             const float* __restrict__ b_ih0,
             const float* __restrict__ w_hh,
             const float* __restrict__ b_hh,
             float* __restrict__ hout) {
    const int tid = threadIdx.x;
    const int g = tid >> 1;          // gate 0..191
    const int kh = tid & 1;          // K half == owned batch row
    const int j = g & 63;
    const int b0 = blockIdx.x * 2;

    __shared__ __align__(16) float h_sh[2][HID];
    __shared__ float rz_sh[2][2][HID];   // [r|z][row][j]
    __shared__ float x_sh[2][2][5];      // [phase][row][c]

    unsigned long long w2[16];
    const ulonglong2* wp = (const ulonglong2*)(w_hh + (size_t)g * HID);
#pragma unroll
    for (int k = 0; k < 8; k++) {
        ulonglong2 v = wp[2 * k + kh];
        w2[2 * k] = v.x; w2[2 * k + 1] = v.y;
    }
    const float bias = b_hh[g];

    float w5[5];
#pragma unroll
    for (int c = 0; c < 5; c++) w5[c] = w_ih0[g * 5 + c];
    const float bi = b_ih0[g];

    if (tid < 2 * HID) ((float*)h_sh)[tid] = 0.f;
    // prologue: stage x(0); prefetch x(1) into reg
    float pfx = 0.f;
    if (tid < 10) {
        const int r = tid / 5, c = tid % 5;
        x_sh[0][r][c] = x[((size_t)(b0 + r) * NT) * 5 + c];
        if (NT > 1) pfx = x[((size_t)(b0 + r) * NT + 1) * 5 + c];
    }
    __syncthreads();

    for (int t = 0; t < NT; t++) {
        const int p = t & 1;

        // stage x(t+1) from reg; prefetch x(t+2)
        if (tid < 10) {
            const int r = tid / 5, c = tid % 5;
            x_sh[p ^ 1][r][c] = pfx;
            if (t + 2 < NT)
                pfx = x[((size_t)(b0 + r) * NT + (t + 2)) * 5 + c];
        }

        // input-side dot for own row: xc = bi + w5 . x(t)[kh]
        float xc = bi;
#pragma unroll
        for (int c = 0; c < 5; c++) xc = fmaf(w5[c], x_sh[p][kh][c], xc);

        // hidden half-dot for both rows
        unsigned long long a0x = 0, a0y = 0, a1x = 0, a1y = 0;
        const ulonglong2* h0 = (const ulonglong2*)h_sh[0];
        const ulonglong2* h1 = (const ulonglong2*)h_sh[1];
#pragma unroll
        for (int k = 0; k < 8; k++) {
            const int c = 2 * k + kh;
            ulonglong2 v0 = h0[c], v1 = h1[c];
            a0x = ffma2(w2[2 * k],     v0.x, a0x);
            a0y = ffma2(w2[2 * k + 1], v0.y, a0y);
            a1x = ffma2(w2[2 * k],     v1.x, a1x);
            a1y = ffma2(w2[2 * k + 1], v1.y, a1y);
        }
        float s0 = f2sum(fadd2(a0x, a0y));
        float s1 = f2sum(fadd2(a1x, a1y));
        s0 += __shfl_xor_sync(0xFFFFFFFFu, s0, 1);
        s1 += __shfl_xor_sync(0xFFFFFFFFu, s1, 1);
        const float sown = bias + (kh ? s1 : s0);

        if (g < 128) {
            const int which = g >> 6;   // 0 = r, 1 = z
            rz_sh[which][kh][j] = sigf(xc + sown);
        }
        __syncthreads();                 // rz + x_sh staged; h reads done

        if (g >= 128) {
            float n = tanh_(xc + rz_sh[0][kh][j] * sown);
            float z = rz_sh[1][kh][j];
            float hp = h_sh[kh][j];
            float hn = n + z * (hp - n);
            h_sh[kh][j] = hn;
            hout[((size_t)t * NB + b0 + kh) * HID + j] = hn;
        }
        __syncthreads();                 // h_sh updated for next step
    }
}

// ---------------------------------------------------------------------------
// Layers 1..4 input GEMM, TF32 tensor cores (proven R12).
// ---------------------------------------------------------------------------
__global__ __launch_bounds__(384, 2)
void k_inp_tc(const float* __restrict__ hin,
              const float* __restrict__ w_ih,
              const float* __restrict__ b_ih,
              float* __restrict__ xg) {
    const int tid = threadIdx.x;
    const int wid = tid >> 5;        // 0..11
    const int lane = tid & 31;
    const int grp = lane >> 2;       // 0..7
    const int tig = lane & 3;        // 0..3
    const size_t row0 = (size_t)blockIdx.x * 128;

    __shared__ __align__(16) float Hs[128][68];

    unsigned wb[2][8][2];
    float bias0[2], bias1[2];
#pragma unroll
    for (int gh = 0; gh < 2; gh++) {
        const int gbase = wid * 16 + gh * 8;
        const float* wrow = w_ih + (size_t)(gbase + grp) * HID;
#pragma unroll
        for (int kb = 0; kb < 8; kb++) {
            wb[gh][kb][0] = cvt_tf32(wrow[kb * 8 + tig]);
            wb[gh][kb][1] = cvt_tf32(wrow[kb * 8 + tig + 4]);
        }
        bias0[gh] = b_ih[gbase + 2 * tig];
        bias1[gh] = b_ih[gbase + 2 * tig + 1];
    }

    for (int i = tid; i < 128 * 16; i += 384) {
        const int r = i >> 4, c4 = (i & 15) * 4;
        float4 v = ((const float4*)(hin + (row0 + r) * HID))[i & 15];
        Hs[r][c4 + 0] = __uint_as_float(cvt_tf32(v.x));
        Hs[r][c4 + 1] = __uint_as_float(cvt_tf32(v.y));
        Hs[r][c4 + 2] = __uint_as_float(cvt_tf32(v.z));
        Hs[r][c4 + 3] = __uint_as_float(cvt_tf32(v.w));
    }
    __syncthreads();

#pragma unroll 1
    for (int rt = 0; rt < 8; rt++) {
        const int r0 = rt * 16;
        float acc[2][4];
#pragma unroll
        for (int gh = 0; gh < 2; gh++) {
            acc[gh][0] = bias0[gh]; acc[gh][1] = bias1[gh];
            acc[gh][2] = bias0[gh]; acc[gh][3] = bias1[gh];
        }
#pragma unroll
        for (int kb = 0; kb < 8; kb++) {
            const int kc = kb * 8 + tig;
            unsigned a0 = __float_as_uint(Hs[r0 + grp][kc]);
            unsigned a1 = __float_as_uint(Hs[r0 + grp + 8][kc]);
            unsigned a2 = __float_as_uint(Hs[r0 + grp][kc + 4]);
            unsigned a3 = __float_as_uint(Hs[r0 + grp + 8][kc + 4]);
            mma_tf32(acc[0], a0, a1, a2, a3, wb[0][kb][0], wb[0][kb][1]);
            mma_tf32(acc[1], a0, a1, a2, a3, wb[1][kb][0], wb[1][kb][1]);
        }
#pragma unroll
        for (int gh = 0; gh < 2; gh++) {
            const int gcol = wid * 16 + gh * 8 + 2 * tig;
            float2* o0 = (float2*)(xg + (row0 + r0 + grp) * NG + gcol);
            *o0 = make_float2(acc[gh][0], acc[gh][1]);
            float2* o1 = (float2*)(xg + (row0 + r0 + grp + 8) * NG + gcol);
            *o1 = make_float2(acc[gh][2], acc[gh][3]);
        }
    }
}

// ---------------------------------------------------------------------------
// Recurrent scan layers 1..4 (proven R10, 627us/layer).
// ---------------------------------------------------------------------------
__global__ __launch_bounds__(384, 2)
void k_scan(const float* __restrict__ w_hh,
            const float* __restrict__ b_hh,
            const float* __restrict__ xg,
            float* __restrict__ hout, int store_all) {
    const int tid = threadIdx.x;
    const int g = tid >> 1;          // gate 0..191
    const int kh = tid & 1;          // K half == owned batch row
    const int j = g & 63;
    const int b0 = blockIdx.x * 2;

    __shared__ __align__(16) float h_sh[2][HID];
    __shared__ float rz_sh[2][2][HID];   // [r|z][row][j]

    unsigned long long w2[16];
    const ulonglong2* wp = (const ulonglong2*)(w_hh + (size_t)g * HID);
#pragma unroll
    for (int k = 0; k < 8; k++) {
        ulonglong2 v = wp[2 * k + kh];
        w2[2 * k] = v.x; w2[2 * k + 1] = v.y;
    }
    const float bias = b_hh[g];

    if (tid < 2 * HID) ((float*)h_sh)[tid] = 0.f;
    __syncthreads();

    const float* xb = xg + ((size_t)b0 + kh) * NG + g;
    float xc = xb[0];

    for (int t = 0; t < NT; t++) {
        float xn = 0.f;
        if (t + 1 < NT) xn = xb[(size_t)(t + 1) * NB * NG];

        unsigned long long a0x = 0, a0y = 0, a1x = 0, a1y = 0;
        const ulonglong2* h0 = (const ulonglong2*)h_sh[0];
        const ulonglong2* h1 = (const ulonglong2*)h_sh[1];
#pragma unroll
        for (int k = 0; k < 8; k++) {
            const int c = 2 * k + kh;
            ulonglong2 v0 = h0[c], v1 = h1[c];
            a0x = ffma2(w2[2 * k],     v0.x, a0x);
            a0y = ffma2(w2[2 * k + 1], v0.y, a0y);
            a1x = ffma2(w2[2 * k],     v1.x, a1x);
            a1y = ffma2(w2[2 * k + 1], v1.y, a1y);
        }
        float s0 = f2sum(fadd2(a0x, a0y));
        float s1 = f2sum(fadd2(a1x, a1y));
        s0 += __shfl_xor_sync(0xFFFFFFFFu, s0, 1);
        s1 += __shfl_xor_sync(0xFFFFFFFFu, s1, 1);
        const float sown = bias + (kh ? s1 : s0);

        if (g < 128) {
            const int which = g >> 6;   // 0 = r, 1 = z
            rz_sh[which][kh][j] = sigf(xc + sown);
        }
        __syncthreads();                 // rz ready; dot reads of h_sh done

        if (g >= 128) {
            float n = tanh_(xc + rz_sh[0][kh][j] * sown);
            float z = rz_sh[1][kh][j];
            float hp = h_sh[kh][j];
            float hn = n + z * (hp - n);
            h_sh[kh][j] = hn;
            if (store_all || t == NT - 1)
                hout[((size_t)t * NB + b0 + kh) * HID + j] = hn;
        }
        __syncthreads();                 // h_sh updated for next step
        xc = xn;
    }
}

// ---------------------------------------------------------------------------
// Final FC on last timestep: out[b] = h[T-1][b][:] . w_fc + b_fc
// ---------------------------------------------------------------------------
__global__ void k_fc(const float* __restrict__ hin,
                     const float* __restrict__ w_fc,
                     const float* __restrict__ b_fc,
                     float* __restrict__ out) {
    int b = blockIdx.x * blockDim.x + threadIdx.x;
    if (b >= NB) return;
    const float* hp = hin + ((size_t)(NT - 1) * NB + b) * HID;
    float acc = b_fc[0];
#pragma unroll
    for (int k = 0; k < HID; k++) acc += hp[k] * w_fc[k];
    out[b] = acc;
}

// ---------------------------------------------------------------------------
extern "C" void kernel_launch(void* const* d_in, const int* in_sizes, int n_in,
                              void* d_out, int out_size) {
    const float* x     = (const float*)d_in[0];
    const float* w_ih0 = (const float*)d_in[1];
    const float* w_hh0 = (const float*)d_in[2];
    const float* b_ih0 = (const float*)d_in[3];
    const float* b_hh0 = (const float*)d_in[4];
    const float* w_ih  = (const float*)d_in[5];   // [4][192][64]
    const float* w_hh  = (const float*)d_in[6];   // [4][192][64]
    const float* b_ih  = (const float*)d_in[7];   // [4][192]
    const float* b_hh  = (const float*)d_in[8];   // [4][192]
    const float* w_fc  = (const float*)d_in[9];
    const float* b_fc  = (const float*)d_in[10];
    float* out = (float*)d_out;

    float *hA, *hB, *xgA, *xgB;
    cudaGetSymbolAddress((void**)&hA, g_h0);
    cudaGetSymbolAddress((void**)&hB, g_h1);
    cudaGetSymbolAddress((void**)&xgA, g_xgA);
    cudaGetSymbolAddress((void**)&xgB, g_xgB);

    // Layer 0: fused input (dim 5) + scan — no xg round-trip, no inp0 kernel.
    k_scan0<<<NB / 2, 384>>>(x, w_ih0, b_ih0, w_hh0, b_hh0, hA);

    // Layers 1..4: TF32 tensor-core input GEMM + fp32 scan
    float* hin = hA;
    float* hou = hB;
    for (int L = 0; L < 4; L++) {
        int last = (L == 3);
        float* xg = (L & 1) ? xgA : xgB;
        k_inp_tc<<<(NT * NB) / 128, 384>>>(hin, w_ih + (size_t)L * NG * HID,
                                           b_ih + L * NG, xg);
        k_scan<<<NB / 2, 384>>>(w_hh + (size_t)L * NG * HID, b_hh + L * NG,
                                xg, hou, !last);
        float* tmp = hin; hin = hou; hou = tmp;
    }

    // FC head on last timestep (hin holds the last layer's output)
    k_fc<<<2, 256>>>(hin, w_fc, b_fc, out);
}